// round 1
// baseline (speedup 1.0000x reference)
#include <cuda_runtime.h>
#include <math.h>

// Problem constants (fixed shapes from setup_inputs)
#define BB 4
#define NN 1024
#define CC 128
#define HH 256
#define WW 256
#define MM 1024            // (H/8)*(W/8) grid cells
#define GRIDC 8
#define TN 32              // query rows per block
#define TM 32              // candidate chunk
#define NTILES (NN / TN)   // 32
#define FOS_BLOCKS (BB * NTILES)   // 128
#define SOS_BLOCKS (BB * NTILES)   // 128

// Scratch (device globals — no allocation allowed)
__device__ float g_a [BB * NN * CC];
__device__ float g_wa[BB * NN * CC];
__device__ float g_gd[BB * MM * CC];
__device__ float g_fos_part[FOS_BLOCKS];
__device__ float g_vis_part[FOS_BLOCKS];
__device__ float g_sos_part[SOS_BLOCKS];

// ---------------------------------------------------------------------------
// Kernel 1: normalize anchors + bilinear-sample & normalize wa / gd.
// One block per descriptor vector; thread = channel.
// ---------------------------------------------------------------------------
__global__ void prep_kernel(const float* __restrict__ kp1_desc,
                            const float* __restrict__ w_kp1,
                            const float* __restrict__ desc2) {
    int idx = blockIdx.x;              // 0 .. B*(2N+M)-1
    const int per_b = 2 * NN + MM;
    int b = idx / per_b;
    int i = idx - b * per_b;
    int c = threadIdx.x;               // 0..127

    float v;
    float* dst;
    if (i < NN) {
        // anchor: normalize kp1_desc row
        v   = kp1_desc[(size_t)(b * NN + i) * CC + c];
        dst = g_a + (size_t)(b * NN + i) * CC;
    } else {
        float px, py;
        if (i < 2 * NN) {
            int n = i - NN;
            px  = w_kp1[(size_t)(b * NN + n) * 2 + 0];
            py  = w_kp1[(size_t)(b * NN + n) * 2 + 1];
            dst = g_wa + (size_t)(b * NN + n) * CC;
        } else {
            int m = i - 2 * NN;
            px  = ((float)(m & 31) + 0.5f) * (float)GRIDC;  // cx
            py  = ((float)(m >> 5) + 0.5f) * (float)GRIDC;  // cy
            dst = g_gd + (size_t)(b * MM + m) * CC;
        }
        float x = fminf(fmaxf(px, 0.0f), (float)(WW - 1));
        float y = fminf(fmaxf(py, 0.0f), (float)(HH - 1));
        float x0f = floorf(x), y0f = floorf(y);
        float wx = x - x0f, wy = y - y0f;
        int x0 = (int)x0f, y0 = (int)y0f;
        int x1 = min(x0 + 1, WW - 1), y1 = min(y0 + 1, HH - 1);
        const float* base = desc2 + (size_t)(b * CC + c) * (HH * WW);
        float v00 = base[y0 * WW + x0];
        float v01 = base[y0 * WW + x1];
        float v10 = base[y1 * WW + x0];
        float v11 = base[y1 * WW + x1];
        v = v00 * (1.0f - wy) * (1.0f - wx) + v01 * (1.0f - wy) * wx
          + v10 * wy * (1.0f - wx)          + v11 * wy * wx;
    }

    // block L2-normalize (128 threads)
    __shared__ float red[4];
    float s = v * v;
    #pragma unroll
    for (int o = 16; o > 0; o >>= 1) s += __shfl_down_sync(0xffffffffu, s, o);
    if ((threadIdx.x & 31) == 0) red[threadIdx.x >> 5] = s;
    __syncthreads();
    float tot = red[0] + red[1] + red[2] + red[3];
    dst[c] = v / (sqrtf(tot) + 1e-8f);
}

// ---------------------------------------------------------------------------
// visibility helper (homography warp of kp1 must stay in bounds)
// ---------------------------------------------------------------------------
__device__ __forceinline__ float compute_vis(const float* __restrict__ kp1,
                                             const float* __restrict__ homo,
                                             int b, int n) {
    float kx = kp1[(size_t)(b * NN + n) * 2 + 0];
    float ky = kp1[(size_t)(b * NN + n) * 2 + 1];
    const float* hm = homo + b * 9;
    float den = hm[6] * kx + hm[7] * ky + hm[8] + 1e-8f;
    float wkx = (hm[0] * kx + hm[1] * ky + hm[2]) / den;
    float wky = (hm[3] * kx + hm[4] * ky + hm[5]) / den;
    return (wkx >= 0.0f && wkx <= (float)(WW - 1) &&
            wky >= 0.0f && wky <= (float)(HH - 1)) ? 1.0f : 0.0f;
}

// ---------------------------------------------------------------------------
// Kernel 2: FOS. Block = 32 keypoints of one batch; stream 1024 grid cells in
// chunks of 32; per-row top-8 smallest masked distances kept in registers.
// ---------------------------------------------------------------------------
__global__ __launch_bounds__(256) void fos_kernel(const float* __restrict__ kp1,
                                                  const float* __restrict__ w_kp1,
                                                  const float* __restrict__ homo) {
    __shared__ float a_s[TN][CC + 4];
    __shared__ float g_s[TM][CC + 4];
    __shared__ float dots[TN][TM + 1];

    int tid = threadIdx.x;
    int b = blockIdx.x / NTILES;
    int n0 = (blockIdx.x - b * NTILES) * TN;

    // load query tile (anchors) into shared
    for (int k = tid; k < TN * (CC / 4); k += 256) {
        int r = k >> 5, cc = (k & 31) << 2;
        *(float4*)&a_s[r][cc] =
            *(const float4*)&g_a[(size_t)(b * NN + n0 + r) * CC + cc];
    }
    __syncthreads();

    float vals[8];
    #pragma unroll
    for (int j = 0; j < 8; j++) vals[j] = 1e30f;
    float worst = 1e30f;
    float pos = 0.0f, visf = 0.0f, qx = 0.0f, qy = 0.0f;

    if (tid < TN) {
        int n = n0 + tid;
        qx = w_kp1[(size_t)(b * NN + n) * 2 + 0];
        qy = w_kp1[(size_t)(b * NN + n) * 2 + 1];
        // pos = || a_n - wa_n ||
        float p = 0.0f;
        const float4* wap = (const float4*)&g_wa[(size_t)(b * NN + n) * CC];
        #pragma unroll 8
        for (int k = 0; k < 32; k++) {
            float4 av = *(float4*)&a_s[tid][k * 4];
            float4 wv = wap[k];
            float d0 = av.x - wv.x, d1 = av.y - wv.y;
            float d2 = av.z - wv.z, d3 = av.w - wv.w;
            p += d0 * d0 + d1 * d1 + d2 * d2 + d3 * d3;
        }
        pos = sqrtf(p);
        visf = compute_vis(kp1, homo, b, n);
    }

    int tx = tid & 15, ty = tid >> 4;

    for (int ch = 0; ch < MM / TM; ch++) {
        __syncthreads();   // protect g_s + dots from previous iteration
        for (int k = tid; k < TM * (CC / 4); k += 256) {
            int r = k >> 5, cc = (k & 31) << 2;
            *(float4*)&g_s[r][cc] =
                *(const float4*)&g_gd[(size_t)(b * MM + ch * TM + r) * CC + cc];
        }
        __syncthreads();

        float acc00 = 0, acc01 = 0, acc10 = 0, acc11 = 0;
        #pragma unroll 8
        for (int k = 0; k < 32; k++) {
            float4 a0 = *(float4*)&a_s[2 * ty][k * 4];
            float4 a1 = *(float4*)&a_s[2 * ty + 1][k * 4];
            float4 g0 = *(float4*)&g_s[2 * tx][k * 4];
            float4 g1 = *(float4*)&g_s[2 * tx + 1][k * 4];
            acc00 += a0.x * g0.x + a0.y * g0.y + a0.z * g0.z + a0.w * g0.w;
            acc01 += a0.x * g1.x + a0.y * g1.y + a0.z * g1.z + a0.w * g1.w;
            acc10 += a1.x * g0.x + a1.y * g0.y + a1.z * g0.z + a1.w * g0.w;
            acc11 += a1.x * g1.x + a1.y * g1.y + a1.z * g1.z + a1.w * g1.w;
        }
        dots[2 * ty][2 * tx]         = acc00;
        dots[2 * ty][2 * tx + 1]     = acc01;
        dots[2 * ty + 1][2 * tx]     = acc10;
        dots[2 * ty + 1][2 * tx + 1] = acc11;
        __syncthreads();

        if (tid < TN) {
            #pragma unroll 4
            for (int col = 0; col < TM; col++) {
                int m = ch * TM + col;
                float gx = (float)((m & 31) * GRIDC + 4);
                float gy = (float)((m >> 5) * GRIDC + 4);
                float dx = qx - gx, dy = qy - gy;
                float d = dots[tid][col];
                float val = (dx * dx + dy * dy < 256.0f)
                          ? 10.0f
                          : sqrtf(fmaxf(2.0f - 2.0f * d, 0.0f) + 1e-8f);
                if (val < worst) {
                    bool done = false;
                    #pragma unroll
                    for (int j = 0; j < 8; j++)
                        if (!done && vals[j] == worst) { vals[j] = val; done = true; }
                    worst = vals[0];
                    #pragma unroll
                    for (int j = 1; j < 8; j++) worst = fmaxf(worst, vals[j]);
                }
            }
        }
    }

    if (tid < TN) {
        float f = 0.0f;
        #pragma unroll
        for (int j = 0; j < 8; j++) f += fmaxf(pos - vals[j] + 1.0f, 0.0f);
        f *= visf;
        float vsum = visf;
        #pragma unroll
        for (int o = 16; o > 0; o >>= 1) {
            f    += __shfl_down_sync(0xffffffffu, f, o);
            vsum += __shfl_down_sync(0xffffffffu, vsum, o);
        }
        if (tid == 0) {
            g_fos_part[blockIdx.x] = f;
            g_vis_part[blockIdx.x] = vsum;
        }
    }
}

// ---------------------------------------------------------------------------
// Kernel 3: SOS. Same tiling over wa x wa; top-8 with indices; then d1 only
// at the 8 gathered indices per row (32x8 = 256 dots per block, one/thread).
// ---------------------------------------------------------------------------
__global__ __launch_bounds__(256) void sos_kernel(const float* __restrict__ kp1,
                                                  const float* __restrict__ w_kp1,
                                                  const float* __restrict__ homo) {
    __shared__ float q_s[TN][CC + 4];
    __shared__ float g_s[TM][CC + 4];
    __shared__ float dots[TN][TM + 1];
    __shared__ float wc_s[TM][2];
    __shared__ float sel_val[TN][8];
    __shared__ int   sel_idx[TN][8];
    __shared__ float term_s[TN][8];

    int tid = threadIdx.x;
    int b = blockIdx.x / NTILES;
    int n0 = (blockIdx.x - b * NTILES) * TN;

    for (int k = tid; k < TN * (CC / 4); k += 256) {
        int r = k >> 5, cc = (k & 31) << 2;
        *(float4*)&q_s[r][cc] =
            *(const float4*)&g_wa[(size_t)(b * NN + n0 + r) * CC + cc];
    }
    __syncthreads();

    float vals[8];
    int   idxs[8];
    #pragma unroll
    for (int j = 0; j < 8; j++) { vals[j] = 1e30f; idxs[j] = 0; }
    float worst = 1e30f;
    float visf = 0.0f, qx = 0.0f, qy = 0.0f;

    if (tid < TN) {
        int n = n0 + tid;
        qx = w_kp1[(size_t)(b * NN + n) * 2 + 0];
        qy = w_kp1[(size_t)(b * NN + n) * 2 + 1];
        visf = compute_vis(kp1, homo, b, n);
    }

    int tx = tid & 15, ty = tid >> 4;

    for (int ch = 0; ch < NN / TM; ch++) {
        __syncthreads();
        for (int k = tid; k < TM * (CC / 4); k += 256) {
            int r = k >> 5, cc = (k & 31) << 2;
            *(float4*)&g_s[r][cc] =
                *(const float4*)&g_wa[(size_t)(b * NN + ch * TM + r) * CC + cc];
        }
        if (tid < TM) {
            wc_s[tid][0] = w_kp1[(size_t)(b * NN + ch * TM + tid) * 2 + 0];
            wc_s[tid][1] = w_kp1[(size_t)(b * NN + ch * TM + tid) * 2 + 1];
        }
        __syncthreads();

        float acc00 = 0, acc01 = 0, acc10 = 0, acc11 = 0;
        #pragma unroll 8
        for (int k = 0; k < 32; k++) {
            float4 a0 = *(float4*)&q_s[2 * ty][k * 4];
            float4 a1 = *(float4*)&q_s[2 * ty + 1][k * 4];
            float4 g0 = *(float4*)&g_s[2 * tx][k * 4];
            float4 g1 = *(float4*)&g_s[2 * tx + 1][k * 4];
            acc00 += a0.x * g0.x + a0.y * g0.y + a0.z * g0.z + a0.w * g0.w;
            acc01 += a0.x * g1.x + a0.y * g1.y + a0.z * g1.z + a0.w * g1.w;
            acc10 += a1.x * g0.x + a1.y * g0.y + a1.z * g0.z + a1.w * g0.w;
            acc11 += a1.x * g1.x + a1.y * g1.y + a1.z * g1.z + a1.w * g1.w;
        }
        dots[2 * ty][2 * tx]         = acc00;
        dots[2 * ty][2 * tx + 1]     = acc01;
        dots[2 * ty + 1][2 * tx]     = acc10;
        dots[2 * ty + 1][2 * tx + 1] = acc11;
        __syncthreads();

        if (tid < TN) {
            int n = n0 + tid;
            #pragma unroll 4
            for (int col = 0; col < TM; col++) {
                int j = ch * TM + col;
                float dx = qx - wc_s[col][0];
                float dy = qy - wc_s[col][1];
                float d = dots[tid][col];
                bool masked = (dx * dx + dy * dy < 256.0f) || (j == n);
                float val = masked ? 10.0f
                                   : sqrtf(fmaxf(2.0f - 2.0f * d, 0.0f) + 1e-8f);
                if (val < worst) {
                    bool done = false;
                    #pragma unroll
                    for (int jj = 0; jj < 8; jj++)
                        if (!done && vals[jj] == worst) {
                            vals[jj] = val; idxs[jj] = j; done = true;
                        }
                    worst = vals[0];
                    #pragma unroll
                    for (int jj = 1; jj < 8; jj++) worst = fmaxf(worst, vals[jj]);
                }
            }
        }
    }

    if (tid < TN) {
        #pragma unroll
        for (int j = 0; j < 8; j++) {
            sel_val[tid][j] = vals[j];
            sel_idx[tid][j] = idxs[j];
        }
    }
    __syncthreads();

    // d1 at gathered indices: one (row, k) per thread (32*8 == 256)
    {
        int row = tid >> 3, k = tid & 7;
        int j = sel_idx[row][k];
        float d2v = sel_val[row][k];
        float term = 0.0f;
        if (d2v < 5.0f) {   // ok mask (d2s < 0.5*BIG)
            const float4* pa = (const float4*)(g_a + (size_t)(b * NN + n0 + row) * CC);
            const float4* pj = (const float4*)(g_a + (size_t)(b * NN + j) * CC);
            float dp = 0.0f;
            #pragma unroll 8
            for (int kk = 0; kk < 32; kk++) {
                float4 x = pa[kk], y = pj[kk];
                dp += x.x * y.x + x.y * y.y + x.z * y.z + x.w * y.w;
            }
            float d1v = sqrtf(fmaxf(2.0f - 2.0f * dp, 0.0f) + 1e-8f);
            term = d1v - d2v;
        }
        term_s[row][k] = term * term;
    }
    __syncthreads();

    if (tid < TN) {
        float s = 0.0f;
        #pragma unroll
        for (int j = 0; j < 8; j++) s += term_s[tid][j];
        float sos_i = sqrtf(s + 1e-8f) * visf;
        #pragma unroll
        for (int o = 16; o > 0; o >>= 1)
            sos_i += __shfl_down_sync(0xffffffffu, sos_i, o);
        if (tid == 0) g_sos_part[blockIdx.x] = sos_i;
    }
}

// ---------------------------------------------------------------------------
// Kernel 4: deterministic final reduction -> scalar loss
// ---------------------------------------------------------------------------
__global__ void finalize_kernel(float* __restrict__ out) {
    if (threadIdx.x == 0 && blockIdx.x == 0) {
        float fos = 0.0f, vis = 0.0f, sos = 0.0f;
        for (int i = 0; i < FOS_BLOCKS; i++) { fos += g_fos_part[i]; vis += g_vis_part[i]; }
        for (int i = 0; i < SOS_BLOCKS; i++) sos += g_sos_part[i];
        float cnt = fmaxf(vis, 1.0f);
        out[0] = fos / (cnt * 8.0f) + sos / cnt;   // LAMBDA = 1
    }
}

// ---------------------------------------------------------------------------
extern "C" void kernel_launch(void* const* d_in, const int* in_sizes, int n_in,
                              void* d_out, int out_size) {
    const float* kp1      = (const float*)d_in[0];
    const float* w_kp1    = (const float*)d_in[1];
    const float* kp1_desc = (const float*)d_in[2];
    const float* desc2    = (const float*)d_in[3];
    const float* homo12   = (const float*)d_in[4];
    (void)in_sizes; (void)n_in; (void)out_size;

    prep_kernel<<<BB * (2 * NN + MM), CC>>>(kp1_desc, w_kp1, desc2);
    fos_kernel<<<FOS_BLOCKS, 256>>>(kp1, w_kp1, homo12);
    sos_kernel<<<SOS_BLOCKS, 256>>>(kp1, w_kp1, homo12);
    finalize_kernel<<<1, 32>>>((float*)d_out);
}

// round 2
// speedup vs baseline: 2.3750x; 2.3750x over previous
#include <cuda_runtime.h>
#include <math.h>

// Problem constants (fixed shapes from setup_inputs)
#define BB 4
#define NN 1024
#define CC 128
#define HH 256
#define WW 256
#define MM 1024
#define GRIDC 8

#define TQ 64              // query rows per block
#define TMC 64             // candidate chunk (cols per inner tile)
#define MSPLIT 4           // candidate splits per query tile
#define COLS_PER_SPLIT (MM / MSPLIT)      // 256
#define CHUNKS (COLS_PER_SPLIT / TMC)     // 4
#define QTILES (NN / TQ)   // 16
#define MAIN_BLOCKS (BB * QTILES * MSPLIT) // 256

// smem tile strides (floats)
#define ST 68              // [k][r] tile row stride (64 + 4 pad, f4-aligned)
#define SD 65              // dots row stride (odd -> conflict-free row-parallel scan)
#define SMEM_FLOATS (128 * ST * 2 + TQ * SD + TQ * 2)
#define SMEM_BYTES (SMEM_FLOATS * 4)

// Scratch (device globals — no allocation allowed)
__device__ float g_a [BB * NN * CC];
__device__ float g_wa[BB * NN * CC];
__device__ float g_gd[BB * MM * CC];
__device__ float g_fos_top [BB * NN * MSPLIT * 8];
__device__ float g_sos_topv[BB * NN * MSPLIT * 8];
__device__ int   g_sos_topi[BB * NN * MSPLIT * 8];
__device__ float g_fos_row[BB * NN];
__device__ float g_vis_row[BB * NN];
__device__ float g_sos_row[BB * NN];

// ---------------------------------------------------------------------------
// Kernel 1: normalize anchors + bilinear-sample & normalize wa / gd.
// ---------------------------------------------------------------------------
__global__ void prep_kernel(const float* __restrict__ kp1_desc,
                            const float* __restrict__ w_kp1,
                            const float* __restrict__ desc2) {
    int idx = blockIdx.x;
    const int per_b = 2 * NN + MM;
    int b = idx / per_b;
    int i = idx - b * per_b;
    int c = threadIdx.x;

    float v;
    float* dst;
    if (i < NN) {
        v   = kp1_desc[(size_t)(b * NN + i) * CC + c];
        dst = g_a + (size_t)(b * NN + i) * CC;
    } else {
        float px, py;
        if (i < 2 * NN) {
            int n = i - NN;
            px  = w_kp1[(size_t)(b * NN + n) * 2 + 0];
            py  = w_kp1[(size_t)(b * NN + n) * 2 + 1];
            dst = g_wa + (size_t)(b * NN + n) * CC;
        } else {
            int m = i - 2 * NN;
            px  = ((float)(m & 31) + 0.5f) * (float)GRIDC;
            py  = ((float)(m >> 5) + 0.5f) * (float)GRIDC;
            dst = g_gd + (size_t)(b * MM + m) * CC;
        }
        float x = fminf(fmaxf(px, 0.0f), (float)(WW - 1));
        float y = fminf(fmaxf(py, 0.0f), (float)(HH - 1));
        float x0f = floorf(x), y0f = floorf(y);
        float wx = x - x0f, wy = y - y0f;
        int x0 = (int)x0f, y0 = (int)y0f;
        int x1 = min(x0 + 1, WW - 1), y1 = min(y0 + 1, HH - 1);
        const float* base = desc2 + (size_t)(b * CC + c) * (HH * WW);
        float v00 = base[y0 * WW + x0];
        float v01 = base[y0 * WW + x1];
        float v10 = base[y1 * WW + x0];
        float v11 = base[y1 * WW + x1];
        v = v00 * (1.0f - wy) * (1.0f - wx) + v01 * (1.0f - wy) * wx
          + v10 * wy * (1.0f - wx)          + v11 * wy * wx;
    }

    __shared__ float red[4];
    float s = v * v;
    #pragma unroll
    for (int o = 16; o > 0; o >>= 1) s += __shfl_down_sync(0xffffffffu, s, o);
    if ((threadIdx.x & 31) == 0) red[threadIdx.x >> 5] = s;
    __syncthreads();
    float tot = red[0] + red[1] + red[2] + red[3];
    dst[c] = v / (sqrtf(tot) + 1e-8f);
}

// ---------------------------------------------------------------------------
// visibility helper
// ---------------------------------------------------------------------------
__device__ __forceinline__ float compute_vis(const float* __restrict__ kp1,
                                             const float* __restrict__ homo,
                                             int b, int n) {
    float kx = kp1[(size_t)(b * NN + n) * 2 + 0];
    float ky = kp1[(size_t)(b * NN + n) * 2 + 1];
    const float* hm = homo + b * 9;
    float den = hm[6] * kx + hm[7] * ky + hm[8] + 1e-8f;
    float wkx = (hm[0] * kx + hm[1] * ky + hm[2]) / den;
    float wky = (hm[3] * kx + hm[4] * ky + hm[5]) / den;
    return (wkx >= 0.0f && wkx <= (float)(WW - 1) &&
            wky >= 0.0f && wky <= (float)(HH - 1)) ? 1.0f : 0.0f;
}

// ---------------------------------------------------------------------------
// Main GEMM + streaming-top8 kernel. IS_SOS=false: a x gd; true: wa x wa.
// Block = 64 queries x 256 candidates (4 chunks of 64).
// Transposed smem tiles [k][row] -> conflict-free LDS in the dot loop.
// ---------------------------------------------------------------------------
template<bool IS_SOS>
__global__ __launch_bounds__(256) void main_kernel(const float* __restrict__ w_kp1) {
    extern __shared__ float sm[];
    float* aT   = sm;                    // [128][ST]
    float* gT   = sm + 128 * ST;         // [128][ST]
    float* dots = gT + 128 * ST;         // [TQ][SD]
    float* wc   = dots + TQ * SD;        // [TMC][2] (sos only)

    int tid = threadIdx.x;
    int bid = blockIdx.x;
    int ms = bid & (MSPLIT - 1);
    int qt = (bid >> 2) & (QTILES - 1);
    int b  = bid >> 6;
    int n0 = qt * TQ;
    int m_base = ms * COLS_PER_SPLIT;

    const float* qsrc = IS_SOS ? g_wa : g_a;
    const float* csrc = IS_SOS ? g_wa : g_gd;

    // load query tile transposed: lanes vary r -> conflict-free STS
    for (int idx = tid; idx < TQ * 32; idx += 256) {
        int r = idx & 63, k4 = idx >> 6;
        float4 v = *(const float4*)&qsrc[(size_t)(b * NN + n0 + r) * CC + 4 * k4];
        aT[(4 * k4 + 0) * ST + r] = v.x;
        aT[(4 * k4 + 1) * ST + r] = v.y;
        aT[(4 * k4 + 2) * ST + r] = v.z;
        aT[(4 * k4 + 3) * ST + r] = v.w;
    }

    // selection state (threads 0..63, one per query row)
    float vals[8];
    int   idxs[8];
    #pragma unroll
    for (int j = 0; j < 8; j++) { vals[j] = 1e30f; idxs[j] = 0; }
    float worst = 1e30f;
    float qx = 0.0f, qy = 0.0f;
    if (tid < TQ) {
        int n = n0 + tid;
        qx = w_kp1[(size_t)(b * NN + n) * 2 + 0];
        qy = w_kp1[(size_t)(b * NN + n) * 2 + 1];
    }

    int tx = tid & 15, ty = tid >> 4;

    for (int ch = 0; ch < CHUNKS; ch++) {
        int m0 = m_base + ch * TMC;
        __syncthreads();   // selection of previous chunk done

        for (int idx = tid; idx < TMC * 32; idx += 256) {
            int r = idx & 63, k4 = idx >> 6;
            float4 v = *(const float4*)&csrc[(size_t)(b * (IS_SOS ? NN : MM) + m0 + r) * CC + 4 * k4];
            gT[(4 * k4 + 0) * ST + r] = v.x;
            gT[(4 * k4 + 1) * ST + r] = v.y;
            gT[(4 * k4 + 2) * ST + r] = v.z;
            gT[(4 * k4 + 3) * ST + r] = v.w;
        }
        if (IS_SOS && tid < 2 * TMC) {
            int c = tid >> 1, xy = tid & 1;
            wc[c * 2 + xy] = w_kp1[(size_t)(b * NN + m0 + c) * 2 + xy];
        }
        __syncthreads();

        float acc00 = 0, acc01 = 0, acc02 = 0, acc03 = 0;
        float acc10 = 0, acc11 = 0, acc12 = 0, acc13 = 0;
        float acc20 = 0, acc21 = 0, acc22 = 0, acc23 = 0;
        float acc30 = 0, acc31 = 0, acc32 = 0, acc33 = 0;
        const float* ap = aT + 4 * ty;
        const float* gp = gT + 4 * tx;
        #pragma unroll 8
        for (int k = 0; k < CC; k++) {
            float4 av = *(const float4*)(ap + k * ST);
            float4 gv = *(const float4*)(gp + k * ST);
            acc00 += av.x * gv.x; acc01 += av.x * gv.y; acc02 += av.x * gv.z; acc03 += av.x * gv.w;
            acc10 += av.y * gv.x; acc11 += av.y * gv.y; acc12 += av.y * gv.z; acc13 += av.y * gv.w;
            acc20 += av.z * gv.x; acc21 += av.z * gv.y; acc22 += av.z * gv.z; acc23 += av.z * gv.w;
            acc30 += av.w * gv.x; acc31 += av.w * gv.y; acc32 += av.w * gv.z; acc33 += av.w * gv.w;
        }
        {
            float* d0 = dots + (4 * ty + 0) * SD + 4 * tx;
            float* d1 = dots + (4 * ty + 1) * SD + 4 * tx;
            float* d2 = dots + (4 * ty + 2) * SD + 4 * tx;
            float* d3 = dots + (4 * ty + 3) * SD + 4 * tx;
            d0[0] = acc00; d0[1] = acc01; d0[2] = acc02; d0[3] = acc03;
            d1[0] = acc10; d1[1] = acc11; d1[2] = acc12; d1[3] = acc13;
            d2[0] = acc20; d2[1] = acc21; d2[2] = acc22; d2[3] = acc23;
            d3[0] = acc30; d3[1] = acc31; d3[2] = acc32; d3[3] = acc33;
        }
        __syncthreads();

        if (tid < TQ) {
            int n = n0 + tid;
            const float* drow = dots + tid * SD;
            #pragma unroll 4
            for (int col = 0; col < TMC; col++) {
                int m = m0 + col;
                float cx, cy;
                bool extra_mask = false;
                if (IS_SOS) {
                    cx = wc[col * 2 + 0];
                    cy = wc[col * 2 + 1];
                    extra_mask = (m == n);
                } else {
                    cx = (float)((m & 31) * GRIDC + 4);
                    cy = (float)((m >> 5) * GRIDC + 4);
                }
                float dx = qx - cx, dy = qy - cy;
                float d = drow[col];
                bool masked = (dx * dx + dy * dy < 256.0f) || extra_mask;
                float val = masked ? 10.0f
                                   : sqrtf(fmaxf(2.0f - 2.0f * d, 0.0f) + 1e-8f);
                if (val < worst) {
                    bool done = false;
                    #pragma unroll
                    for (int j = 0; j < 8; j++)
                        if (!done && vals[j] == worst) {
                            vals[j] = val; idxs[j] = m; done = true;
                        }
                    worst = vals[0];
                    #pragma unroll
                    for (int j = 1; j < 8; j++) worst = fmaxf(worst, vals[j]);
                }
            }
        }
    }

    if (tid < TQ) {
        size_t base = (((size_t)(b * NN + n0 + tid)) * MSPLIT + ms) * 8;
        if (IS_SOS) {
            #pragma unroll
            for (int j = 0; j < 8; j++) {
                g_sos_topv[base + j] = vals[j];
                g_sos_topi[base + j] = idxs[j];
            }
        } else {
            #pragma unroll
            for (int j = 0; j < 8; j++) g_fos_top[base + j] = vals[j];
        }
    }
}

// ---------------------------------------------------------------------------
// merge_fos: warp per row. Merge 4x8 partial top-8, compute pos, vis, term.
// ---------------------------------------------------------------------------
__global__ __launch_bounds__(256) void merge_fos(const float* __restrict__ kp1,
                                                 const float* __restrict__ homo) {
    int w = threadIdx.x >> 5, lane = threadIdx.x & 31;
    int row = blockIdx.x * 8 + w;
    int b = row >> 10, n = row & 1023;

    // pos = || a_row - wa_row ||
    float4 av = *(const float4*)&g_a [(size_t)row * CC + 4 * lane];
    float4 wv = *(const float4*)&g_wa[(size_t)row * CC + 4 * lane];
    float d0 = av.x - wv.x, d1 = av.y - wv.y, d2 = av.z - wv.z, d3 = av.w - wv.w;
    float s = d0 * d0 + d1 * d1 + d2 * d2 + d3 * d3;
    #pragma unroll
    for (int o = 16; o > 0; o >>= 1) s += __shfl_xor_sync(0xffffffffu, s, o);

    if (lane == 0) {
        float pos = sqrtf(s);
        float vis = compute_vis(kp1, homo, b, n);
        float vals[8];
        #pragma unroll
        for (int j = 0; j < 8; j++) vals[j] = 1e30f;
        float worst = 1e30f;
        const float* src = g_fos_top + (size_t)row * MSPLIT * 8;
        for (int i = 0; i < MSPLIT * 8; i++) {
            float val = src[i];
            if (val < worst) {
                bool done = false;
                #pragma unroll
                for (int j = 0; j < 8; j++)
                    if (!done && vals[j] == worst) { vals[j] = val; done = true; }
                worst = vals[0];
                #pragma unroll
                for (int j = 1; j < 8; j++) worst = fmaxf(worst, vals[j]);
            }
        }
        float f = 0.0f;
        #pragma unroll
        for (int j = 0; j < 8; j++) f += fmaxf(pos - vals[j] + 1.0f, 0.0f);
        g_fos_row[row] = f * vis;
        g_vis_row[row] = vis;
    }
}

// ---------------------------------------------------------------------------
// merge_sos: warp per row. Merge top-8 (+idx), gather d1 dots, compute sos_i.
// ---------------------------------------------------------------------------
__global__ __launch_bounds__(256) void merge_sos(const float* __restrict__ kp1,
                                                 const float* __restrict__ homo) {
    __shared__ float sv[8][8];
    __shared__ int   si[8][8];
    __shared__ float tt[8][8];

    int w = threadIdx.x >> 5, lane = threadIdx.x & 31;
    int row = blockIdx.x * 8 + w;
    int b = row >> 10, n = row & 1023;

    if (lane == 0) {
        float vals[8]; int idxsr[8];
        #pragma unroll
        for (int j = 0; j < 8; j++) { vals[j] = 1e30f; idxsr[j] = 0; }
        float worst = 1e30f;
        const float* srcv = g_sos_topv + (size_t)row * MSPLIT * 8;
        const int*   srci = g_sos_topi + (size_t)row * MSPLIT * 8;
        for (int i = 0; i < MSPLIT * 8; i++) {
            float val = srcv[i];
            if (val < worst) {
                int ii = srci[i];
                bool done = false;
                #pragma unroll
                for (int j = 0; j < 8; j++)
                    if (!done && vals[j] == worst) {
                        vals[j] = val; idxsr[j] = ii; done = true;
                    }
                worst = vals[0];
                #pragma unroll
                for (int j = 1; j < 8; j++) worst = fmaxf(worst, vals[j]);
            }
        }
        #pragma unroll
        for (int j = 0; j < 8; j++) { sv[w][j] = vals[j]; si[w][j] = idxsr[j]; }
    }
    __syncwarp();

    // d1 dots: lanes split 8 dots x 4-lane quads
    {
        int j = lane >> 2, q = lane & 3;
        int cidx = si[w][j];
        const float4* pa = (const float4*)(g_a + (size_t)row * CC);
        const float4* pb = (const float4*)(g_a + (size_t)(b * NN + cidx) * CC);
        float dp = 0.0f;
        #pragma unroll
        for (int kk = 0; kk < 8; kk++) {
            float4 x = pa[q * 8 + kk], y = pb[q * 8 + kk];
            dp += x.x * y.x + x.y * y.y + x.z * y.z + x.w * y.w;
        }
        dp += __shfl_xor_sync(0xffffffffu, dp, 1);
        dp += __shfl_xor_sync(0xffffffffu, dp, 2);
        if (q == 0) {
            float d2v = sv[w][j];
            float d1v = sqrtf(fmaxf(2.0f - 2.0f * dp, 0.0f) + 1e-8f);
            float t = (d2v < 5.0f) ? (d1v - d2v) : 0.0f;
            tt[w][j] = t * t;
        }
    }
    __syncwarp();

    if (lane == 0) {
        float ssum = 0.0f;
        #pragma unroll
        for (int j = 0; j < 8; j++) ssum += tt[w][j];
        float vis = compute_vis(kp1, homo, b, n);
        g_sos_row[row] = sqrtf(ssum + 1e-8f) * vis;
    }
}

// ---------------------------------------------------------------------------
// finalize: deterministic tree reduction over 4096 rows.
// ---------------------------------------------------------------------------
__global__ void finalize_kernel(float* __restrict__ out) {
    __shared__ float sf[1024], sv[1024], ss[1024];
    int t = threadIdx.x;
    float f = 0.0f, v = 0.0f, s = 0.0f;
    #pragma unroll
    for (int i = 0; i < 4; i++) {
        f += g_fos_row[t + 1024 * i];
        v += g_vis_row[t + 1024 * i];
        s += g_sos_row[t + 1024 * i];
    }
    sf[t] = f; sv[t] = v; ss[t] = s;
    __syncthreads();
    for (int o = 512; o > 0; o >>= 1) {
        if (t < o) {
            sf[t] += sf[t + o];
            sv[t] += sv[t + o];
            ss[t] += ss[t + o];
        }
        __syncthreads();
    }
    if (t == 0) {
        float cnt = fmaxf(sv[0], 1.0f);
        out[0] = sf[0] / (cnt * 8.0f) + ss[0] / cnt;
    }
}

// ---------------------------------------------------------------------------
extern "C" void kernel_launch(void* const* d_in, const int* in_sizes, int n_in,
                              void* d_out, int out_size) {
    const float* kp1      = (const float*)d_in[0];
    const float* w_kp1    = (const float*)d_in[1];
    const float* kp1_desc = (const float*)d_in[2];
    const float* desc2    = (const float*)d_in[3];
    const float* homo12   = (const float*)d_in[4];
    (void)in_sizes; (void)n_in; (void)out_size;

    cudaFuncSetAttribute(main_kernel<false>,
                         cudaFuncAttributeMaxDynamicSharedMemorySize, SMEM_BYTES);
    cudaFuncSetAttribute(main_kernel<true>,
                         cudaFuncAttributeMaxDynamicSharedMemorySize, SMEM_BYTES);

    prep_kernel<<<BB * (2 * NN + MM), CC>>>(kp1_desc, w_kp1, desc2);
    main_kernel<false><<<MAIN_BLOCKS, 256, SMEM_BYTES>>>(w_kp1);
    main_kernel<true ><<<MAIN_BLOCKS, 256, SMEM_BYTES>>>(w_kp1);
    merge_fos<<<BB * NN / 8, 256>>>(kp1, homo12);
    merge_sos<<<BB * NN / 8, 256>>>(kp1, homo12);
    finalize_kernel<<<1, 1024>>>((float*)d_out);
}

// round 3
// speedup vs baseline: 3.1653x; 1.3327x over previous
#include <cuda_runtime.h>
#include <math.h>

// Problem constants (fixed shapes from setup_inputs)
#define BB 4
#define NN 1024
#define CC 128
#define HH 256
#define WW 256
#define MM 1024
#define GRIDC 8

#define TQ 64              // query rows per block
#define TMC 64             // candidate chunk (cols per inner tile)
#define MSPLIT 4           // candidate splits per query tile
#define COLS_PER_SPLIT (MM / MSPLIT)      // 256
#define CHUNKS (COLS_PER_SPLIT / TMC)     // 4
#define QTILES (NN / TQ)   // 16
#define HALF_BLOCKS (BB * QTILES * MSPLIT) // 256 (per loss term)
#define MAIN_BLOCKS (2 * HALF_BLOCKS)      // 512

// smem tile strides (floats)
#define ST 68              // [k][r] tile row stride (64 + 4 pad, f4-aligned)
#define SD 65              // dots row stride
#define SSEL 33            // per-row partial-top8 stride (32 + 1 pad)
#define SMEM_FLOATS (128 * ST * 2 + TQ * SD + TQ * SSEL * 2 + 2 * TMC)
#define SMEM_BYTES (SMEM_FLOATS * 4)

// Scratch (device globals — no allocation allowed)
__device__ float g_a [BB * NN * CC];
__device__ float g_wa[BB * NN * CC];
__device__ float g_gd[BB * MM * CC];
__device__ float g_fos_top [BB * NN * MSPLIT * 8];
__device__ float g_sos_topv[BB * NN * MSPLIT * 8];
__device__ int   g_sos_topi[BB * NN * MSPLIT * 8];
__device__ float g_fos_row[BB * NN];
__device__ float g_vis_row[BB * NN];
__device__ float g_sos_row[BB * NN];

// ---------------------------------------------------------------------------
// Kernel 1: normalize anchors + bilinear-sample & normalize wa / gd.
// ---------------------------------------------------------------------------
__global__ void prep_kernel(const float* __restrict__ kp1_desc,
                            const float* __restrict__ w_kp1,
                            const float* __restrict__ desc2) {
    int idx = blockIdx.x;
    const int per_b = 2 * NN + MM;
    int b = idx / per_b;
    int i = idx - b * per_b;
    int c = threadIdx.x;

    float v;
    float* dst;
    if (i < NN) {
        v   = kp1_desc[(size_t)(b * NN + i) * CC + c];
        dst = g_a + (size_t)(b * NN + i) * CC;
    } else {
        float px, py;
        if (i < 2 * NN) {
            int n = i - NN;
            px  = w_kp1[(size_t)(b * NN + n) * 2 + 0];
            py  = w_kp1[(size_t)(b * NN + n) * 2 + 1];
            dst = g_wa + (size_t)(b * NN + n) * CC;
        } else {
            int m = i - 2 * NN;
            px  = ((float)(m & 31) + 0.5f) * (float)GRIDC;
            py  = ((float)(m >> 5) + 0.5f) * (float)GRIDC;
            dst = g_gd + (size_t)(b * MM + m) * CC;
        }
        float x = fminf(fmaxf(px, 0.0f), (float)(WW - 1));
        float y = fminf(fmaxf(py, 0.0f), (float)(HH - 1));
        float x0f = floorf(x), y0f = floorf(y);
        float wx = x - x0f, wy = y - y0f;
        int x0 = (int)x0f, y0 = (int)y0f;
        int x1 = min(x0 + 1, WW - 1), y1 = min(y0 + 1, HH - 1);
        const float* base = desc2 + (size_t)(b * CC + c) * (HH * WW);
        float v00 = base[y0 * WW + x0];
        float v01 = base[y0 * WW + x1];
        float v10 = base[y1 * WW + x0];
        float v11 = base[y1 * WW + x1];
        v = v00 * (1.0f - wy) * (1.0f - wx) + v01 * (1.0f - wy) * wx
          + v10 * wy * (1.0f - wx)          + v11 * wy * wx;
    }

    __shared__ float red[4];
    float s = v * v;
    #pragma unroll
    for (int o = 16; o > 0; o >>= 1) s += __shfl_down_sync(0xffffffffu, s, o);
    if ((threadIdx.x & 31) == 0) red[threadIdx.x >> 5] = s;
    __syncthreads();
    float tot = red[0] + red[1] + red[2] + red[3];
    dst[c] = v / (sqrtf(tot) + 1e-8f);
}

// ---------------------------------------------------------------------------
// visibility helper
// ---------------------------------------------------------------------------
__device__ __forceinline__ float compute_vis(const float* __restrict__ kp1,
                                             const float* __restrict__ homo,
                                             int b, int n) {
    float kx = kp1[(size_t)(b * NN + n) * 2 + 0];
    float ky = kp1[(size_t)(b * NN + n) * 2 + 1];
    const float* hm = homo + b * 9;
    float den = hm[6] * kx + hm[7] * ky + hm[8] + 1e-8f;
    float wkx = (hm[0] * kx + hm[1] * ky + hm[2]) / den;
    float wky = (hm[3] * kx + hm[4] * ky + hm[5]) / den;
    return (wkx >= 0.0f && wkx <= (float)(WW - 1) &&
            wky >= 0.0f && wky <= (float)(HH - 1)) ? 1.0f : 0.0f;
}

// ---------------------------------------------------------------------------
// Main GEMM + streaming-top8. Blocks [0,256): FOS (a x gd); [256,512): SOS
// (wa x wa). 64 queries x 256 candidates per block. Transposed smem tiles.
// Selection is 4-way parallel per row (thread quarter scans 16 cols/chunk).
// ---------------------------------------------------------------------------
__global__ __launch_bounds__(256) void main_kernel(const float* __restrict__ w_kp1) {
    extern __shared__ float sm[];
    float* aT   = sm;                    // [128][ST]
    float* gT   = sm + 128 * ST;         // [128][ST]
    float* dots = gT + 128 * ST;         // [TQ][SD]
    float* selv = dots + TQ * SD;        // [TQ][SSEL]
    float* seli = selv + TQ * SSEL;      // [TQ][SSEL] (int bits)
    float* wc   = seli + TQ * SSEL;      // [TMC][2] (sos only)

    int tid = threadIdx.x;
    int bid = blockIdx.x;
    bool is_sos = bid >= HALF_BLOCKS;
    int lbid = is_sos ? bid - HALF_BLOCKS : bid;
    int ms = lbid & (MSPLIT - 1);
    int qt = (lbid >> 2) & (QTILES - 1);
    int b  = lbid >> 6;
    int n0 = qt * TQ;
    int m_base = ms * COLS_PER_SPLIT;

    const float* qsrc = is_sos ? g_wa : g_a;
    const float* csrc = is_sos ? g_wa : g_gd;
    const int crows = is_sos ? NN : MM;

    // load query tile transposed
    for (int idx = tid; idx < TQ * 32; idx += 256) {
        int r = idx & 63, k4 = idx >> 6;
        float4 v = *(const float4*)&qsrc[(size_t)(b * NN + n0 + r) * CC + 4 * k4];
        aT[(4 * k4 + 0) * ST + r] = v.x;
        aT[(4 * k4 + 1) * ST + r] = v.y;
        aT[(4 * k4 + 2) * ST + r] = v.z;
        aT[(4 * k4 + 3) * ST + r] = v.w;
    }

    // selection state: 4 threads per row; thread quarter q scans 16 cols/chunk
    int selr = tid >> 2, selq = tid & 3;
    float vals[8];
    int   idxs[8];
    #pragma unroll
    for (int j = 0; j < 8; j++) { vals[j] = 1e30f; idxs[j] = 0; }
    float worst = 1e30f;
    float qx = w_kp1[(size_t)(b * NN + n0 + selr) * 2 + 0];
    float qy = w_kp1[(size_t)(b * NN + n0 + selr) * 2 + 1];
    int n_self = n0 + selr;

    int tx = tid & 15, ty = tid >> 4;

    for (int ch = 0; ch < CHUNKS; ch++) {
        int m0 = m_base + ch * TMC;
        __syncthreads();   // previous chunk fully consumed

        for (int idx = tid; idx < TMC * 32; idx += 256) {
            int r = idx & 63, k4 = idx >> 6;
            float4 v = *(const float4*)&csrc[(size_t)(b * crows + m0 + r) * CC + 4 * k4];
            gT[(4 * k4 + 0) * ST + r] = v.x;
            gT[(4 * k4 + 1) * ST + r] = v.y;
            gT[(4 * k4 + 2) * ST + r] = v.z;
            gT[(4 * k4 + 3) * ST + r] = v.w;
        }
        if (is_sos && tid < 2 * TMC) {
            int c = tid >> 1, xy = tid & 1;
            wc[c * 2 + xy] = w_kp1[(size_t)(b * NN + m0 + c) * 2 + xy];
        }
        __syncthreads();

        float acc00 = 0, acc01 = 0, acc02 = 0, acc03 = 0;
        float acc10 = 0, acc11 = 0, acc12 = 0, acc13 = 0;
        float acc20 = 0, acc21 = 0, acc22 = 0, acc23 = 0;
        float acc30 = 0, acc31 = 0, acc32 = 0, acc33 = 0;
        const float* ap = aT + 4 * ty;
        const float* gp = gT + 4 * tx;
        #pragma unroll 8
        for (int k = 0; k < CC; k++) {
            float4 av = *(const float4*)(ap + k * ST);
            float4 gv = *(const float4*)(gp + k * ST);
            acc00 += av.x * gv.x; acc01 += av.x * gv.y; acc02 += av.x * gv.z; acc03 += av.x * gv.w;
            acc10 += av.y * gv.x; acc11 += av.y * gv.y; acc12 += av.y * gv.z; acc13 += av.y * gv.w;
            acc20 += av.z * gv.x; acc21 += av.z * gv.y; acc22 += av.z * gv.z; acc23 += av.z * gv.w;
            acc30 += av.w * gv.x; acc31 += av.w * gv.y; acc32 += av.w * gv.z; acc33 += av.w * gv.w;
        }
        {
            float* d0 = dots + (4 * ty + 0) * SD + 4 * tx;
            float* d1 = dots + (4 * ty + 1) * SD + 4 * tx;
            float* d2 = dots + (4 * ty + 2) * SD + 4 * tx;
            float* d3 = dots + (4 * ty + 3) * SD + 4 * tx;
            d0[0] = acc00; d0[1] = acc01; d0[2] = acc02; d0[3] = acc03;
            d1[0] = acc10; d1[1] = acc11; d1[2] = acc12; d1[3] = acc13;
            d2[0] = acc20; d2[1] = acc21; d2[2] = acc22; d2[3] = acc23;
            d3[0] = acc30; d3[1] = acc31; d3[2] = acc32; d3[3] = acc33;
        }
        __syncthreads();

        // parallel selection: 4 threads per row, 16 cols each
        {
            const float* drow = dots + selr * SD + selq * 16;
            #pragma unroll 4
            for (int ii = 0; ii < 16; ii++) {
                int col = selq * 16 + ii;
                int m = m0 + col;
                float cx, cy;
                bool extra_mask = false;
                if (is_sos) {
                    cx = wc[col * 2 + 0];
                    cy = wc[col * 2 + 1];
                    extra_mask = (m == n_self);
                } else {
                    cx = (float)((m & 31) * GRIDC + 4);
                    cy = (float)((m >> 5) * GRIDC + 4);
                }
                float dx = qx - cx, dy = qy - cy;
                float d = drow[ii];
                bool masked = (dx * dx + dy * dy < 256.0f) || extra_mask;
                float val = masked ? 10.0f
                                   : sqrtf(fmaxf(2.0f - 2.0f * d, 0.0f) + 1e-8f);
                if (val < worst) {
                    bool done = false;
                    #pragma unroll
                    for (int j = 0; j < 8; j++)
                        if (!done && vals[j] == worst) {
                            vals[j] = val; idxs[j] = m; done = true;
                        }
                    worst = vals[0];
                    #pragma unroll
                    for (int j = 1; j < 8; j++) worst = fmaxf(worst, vals[j]);
                }
            }
        }
    }

    // write per-thread partial top-8 (tid == selr*4 + selq)
    __syncthreads();
    {
        float* pv = selv + selr * SSEL + selq * 8;
        int*   pi = (int*)(seli + selr * SSEL) + selq * 8;
        #pragma unroll
        for (int j = 0; j < 8; j++) { pv[j] = vals[j]; pi[j] = idxs[j]; }
    }
    __syncthreads();

    // final per-row merge: thread r merges its row's 32 partials -> top-8
    if (tid < TQ) {
        float mv[8]; int mi[8];
        #pragma unroll
        for (int j = 0; j < 8; j++) { mv[j] = 1e30f; mi[j] = 0; }
        float w8 = 1e30f;
        const float* pv = selv + tid * SSEL;
        const int*   pi = (const int*)(seli + tid * SSEL);
        #pragma unroll 4
        for (int i = 0; i < 32; i++) {
            float val = pv[i];
            if (val < w8) {
                int ii = pi[i];
                bool done = false;
                #pragma unroll
                for (int j = 0; j < 8; j++)
                    if (!done && mv[j] == w8) { mv[j] = val; mi[j] = ii; done = true; }
                w8 = mv[0];
                #pragma unroll
                for (int j = 1; j < 8; j++) w8 = fmaxf(w8, mv[j]);
            }
        }
        size_t base = (((size_t)(b * NN + n0 + tid)) * MSPLIT + ms) * 8;
        if (is_sos) {
            #pragma unroll
            for (int j = 0; j < 8; j++) {
                g_sos_topv[base + j] = mv[j];
                g_sos_topi[base + j] = mi[j];
            }
        } else {
            #pragma unroll
            for (int j = 0; j < 8; j++) g_fos_top[base + j] = mv[j];
        }
    }
}

// ---------------------------------------------------------------------------
// Warp bitonic sort (32 keys ascending, with payload)
// ---------------------------------------------------------------------------
__device__ __forceinline__ void bitonic32(float& v, int& i) {
    unsigned lane = threadIdx.x & 31;
    #pragma unroll
    for (int k = 2; k <= 32; k <<= 1) {
        #pragma unroll
        for (int j = k >> 1; j > 0; j >>= 1) {
            float pv = __shfl_xor_sync(0xffffffffu, v, j);
            int   pi = __shfl_xor_sync(0xffffffffu, i, j);
            bool up = ((lane & k) == 0) || (k == 32);
            bool keepmin = (up == ((lane & j) == 0));
            bool take = keepmin ? (pv < v) : (pv > v);
            if (take) { v = pv; i = pi; }
        }
    }
}

// ---------------------------------------------------------------------------
// Fused epilogue: warp per row; bitonic merges for FOS and SOS, pos, vis,
// d1 gather; writes row-level partials.
// ---------------------------------------------------------------------------
__global__ __launch_bounds__(256) void epilogue_kernel(const float* __restrict__ kp1,
                                                       const float* __restrict__ homo) {
    int w = threadIdx.x >> 5, lane = threadIdx.x & 31;
    int row = blockIdx.x * 8 + w;
    int b = row >> 10, n = row & 1023;

    // pos = || a_row - wa_row || (full warp)
    float4 av = *(const float4*)&g_a [(size_t)row * CC + 4 * lane];
    float4 wv = *(const float4*)&g_wa[(size_t)row * CC + 4 * lane];
    float d0 = av.x - wv.x, d1 = av.y - wv.y, d2 = av.z - wv.z, d3 = av.w - wv.w;
    float s = d0 * d0 + d1 * d1 + d2 * d2 + d3 * d3;
    #pragma unroll
    for (int o = 16; o > 0; o >>= 1) s += __shfl_xor_sync(0xffffffffu, s, o);
    float pos = sqrtf(s);

    // ---- FOS merge: 32 partial values -> sorted, lanes 0..7 smallest ----
    float fv = g_fos_top[(size_t)row * 32 + lane];
    int   fi = 0;
    bitonic32(fv, fi);
    float f = (lane < 8) ? fmaxf(pos - fv + 1.0f, 0.0f) : 0.0f;
    #pragma unroll
    for (int o = 16; o > 0; o >>= 1) f += __shfl_xor_sync(0xffffffffu, f, o);

    // ---- SOS merge ----
    float sv = g_sos_topv[(size_t)row * 32 + lane];
    int   si = g_sos_topi[(size_t)row * 32 + lane];
    bitonic32(sv, si);

    // d1 at the 8 selected indices: quad (4 lanes) per index
    int j = lane >> 2, q = lane & 3;
    float d2v = __shfl_sync(0xffffffffu, sv, j);
    int cidx  = __shfl_sync(0xffffffffu, si, j);
    const float4* pa = (const float4*)(g_a + (size_t)row * CC);
    const float4* pb = (const float4*)(g_a + (size_t)(b * NN + cidx) * CC);
    float dp = 0.0f;
    #pragma unroll
    for (int kk = 0; kk < 8; kk++) {
        float4 x = pa[q * 8 + kk], y = pb[q * 8 + kk];
        dp += x.x * y.x + x.y * y.y + x.z * y.z + x.w * y.w;
    }
    dp += __shfl_xor_sync(0xffffffffu, dp, 1);
    dp += __shfl_xor_sync(0xffffffffu, dp, 2);
    float d1v = sqrtf(fmaxf(2.0f - 2.0f * dp, 0.0f) + 1e-8f);
    float t = (d2v < 5.0f) ? (d1v - d2v) : 0.0f;
    float t2 = (q == 0) ? t * t : 0.0f;
    #pragma unroll
    for (int o = 16; o > 0; o >>= 1) t2 += __shfl_xor_sync(0xffffffffu, t2, o);

    if (lane == 0) {
        float vis = compute_vis(kp1, homo, b, n);
        g_fos_row[row] = f * vis;
        g_vis_row[row] = vis;
        g_sos_row[row] = sqrtf(t2 + 1e-8f) * vis;
    }
}

// ---------------------------------------------------------------------------
// finalize: deterministic tree reduction over 4096 rows.
// ---------------------------------------------------------------------------
__global__ void finalize_kernel(float* __restrict__ out) {
    __shared__ float sf[1024], sv[1024], ss[1024];
    int t = threadIdx.x;
    float f = 0.0f, v = 0.0f, s = 0.0f;
    #pragma unroll
    for (int i = 0; i < 4; i++) {
        f += g_fos_row[t + 1024 * i];
        v += g_vis_row[t + 1024 * i];
        s += g_sos_row[t + 1024 * i];
    }
    sf[t] = f; sv[t] = v; ss[t] = s;
    __syncthreads();
    for (int o = 512; o > 0; o >>= 1) {
        if (t < o) {
            sf[t] += sf[t + o];
            sv[t] += sv[t + o];
            ss[t] += ss[t + o];
        }
        __syncthreads();
    }
    if (t == 0) {
        float cnt = fmaxf(sv[0], 1.0f);
        out[0] = sf[0] / (cnt * 8.0f) + ss[0] / cnt;
    }
}

// ---------------------------------------------------------------------------
extern "C" void kernel_launch(void* const* d_in, const int* in_sizes, int n_in,
                              void* d_out, int out_size) {
    const float* kp1      = (const float*)d_in[0];
    const float* w_kp1    = (const float*)d_in[1];
    const float* kp1_desc = (const float*)d_in[2];
    const float* desc2    = (const float*)d_in[3];
    const float* homo12   = (const float*)d_in[4];
    (void)in_sizes; (void)n_in; (void)out_size;

    cudaFuncSetAttribute(main_kernel,
                         cudaFuncAttributeMaxDynamicSharedMemorySize, SMEM_BYTES);

    prep_kernel<<<BB * (2 * NN + MM), CC>>>(kp1_desc, w_kp1, desc2);
    main_kernel<<<MAIN_BLOCKS, 256, SMEM_BYTES>>>(w_kp1);
    epilogue_kernel<<<BB * NN / 8, 256>>>(kp1, homo12);
    finalize_kernel<<<1, 1024>>>((float*)d_out);
}

// round 4
// speedup vs baseline: 3.3059x; 1.0444x over previous
#include <cuda_runtime.h>
#include <math.h>

// Problem constants (fixed shapes from setup_inputs)
#define BB 4
#define NN 1024
#define CC 128
#define HH 256
#define WW 256
#define MM 1024
#define GRIDC 8

#define TQ 64              // query rows per block
#define TMC 64             // candidate chunk
#define MSPLIT 4
#define COLS_PER_SPLIT (MM / MSPLIT)      // 256
#define CHUNKS (COLS_PER_SPLIT / TMC)     // 4
#define QTILES (NN / TQ)   // 16
#define HALF_BLOCKS (BB * QTILES * MSPLIT) // 256
#define MAIN_BLOCKS (2 * HALF_BLOCKS)      // 512

#define ST 68              // [k][r] tile row stride
#define SD 66              // dots row stride (even: 8B stores ok; 264B rows stagger banks)
// smem: aT 128*ST + gT 128*ST + dbuf 2*64*SD + qxy 128 + wc 128
#define SMEM_FLOATS (128 * ST * 2 + 2 * 64 * SD + 128 + 128)
#define SMEM_BYTES (SMEM_FLOATS * 4)

#define PACK2(dst, x) asm("mov.b64 %0, {%1, %1};" : "=l"(dst) : "r"(__float_as_uint(x)))
#define FMA2(acc, a, b) asm("fma.rn.f32x2 %0, %1, %2, %0;" : "+l"(acc) : "l"(a), "l"(b))
#define UNPACK2(lo, hi, v) asm("mov.b64 {%0, %1}, %2;" : "=f"(lo), "=f"(hi) : "l"(v))

// Scratch (device globals — no allocation allowed)
__device__ float g_a [BB * NN * CC];
__device__ float g_wa[BB * NN * CC];
__device__ float g_gd[BB * MM * CC];
__device__ float g_fos_top [BB * NN * MSPLIT * 8];   // dots
__device__ float g_sos_topv[BB * NN * MSPLIT * 8];   // dots
__device__ int   g_sos_topi[BB * NN * MSPLIT * 8];
__device__ float g_fos_row[BB * NN];
__device__ float g_vis_row[BB * NN];
__device__ float g_sos_row[BB * NN];

// ---------------------------------------------------------------------------
// Prep kernels: normalize anchors; bilinear-sample + normalize wa / gd.
// ---------------------------------------------------------------------------
__global__ void prep_a_kernel(const float* __restrict__ kp1_desc) {
    int c = threadIdx.x;
    float v = kp1_desc[(size_t)blockIdx.x * CC + c];
    __shared__ float red[4];
    float s = v * v;
    #pragma unroll
    for (int o = 16; o > 0; o >>= 1) s += __shfl_down_sync(0xffffffffu, s, o);
    if ((c & 31) == 0) red[c >> 5] = s;
    __syncthreads();
    float tot = red[0] + red[1] + red[2] + red[3];
    g_a[(size_t)blockIdx.x * CC + c] = v / (sqrtf(tot) + 1e-8f);
}

template<bool GD>
__global__ void prep_bil_kernel(const float* __restrict__ w_kp1,
                                const float* __restrict__ desc2) {
    int idx = blockIdx.x;             // b * (NN or MM) + point
    int c = threadIdx.x;
    int b, px_i;
    float px, py;
    if (GD) {
        b = idx / MM; int m = idx - b * MM;
        px = ((float)(m & 31) + 0.5f) * (float)GRIDC;
        py = ((float)(m >> 5) + 0.5f) * (float)GRIDC;
        (void)px_i;
    } else {
        b = idx / NN; int n = idx - b * NN;
        px = w_kp1[(size_t)(b * NN + n) * 2 + 0];
        py = w_kp1[(size_t)(b * NN + n) * 2 + 1];
    }
    float x = fminf(fmaxf(px, 0.0f), (float)(WW - 1));
    float y = fminf(fmaxf(py, 0.0f), (float)(HH - 1));
    float x0f = floorf(x), y0f = floorf(y);
    float wx = x - x0f, wy = y - y0f;
    int x0 = (int)x0f, y0 = (int)y0f;
    int x1 = min(x0 + 1, WW - 1), y1 = min(y0 + 1, HH - 1);
    const float* base = desc2 + (size_t)(b * CC + c) * (HH * WW);
    float v00 = base[y0 * WW + x0];
    float v01 = base[y0 * WW + x1];
    float v10 = base[y1 * WW + x0];
    float v11 = base[y1 * WW + x1];
    float v = v00 * (1.0f - wy) * (1.0f - wx) + v01 * (1.0f - wy) * wx
            + v10 * wy * (1.0f - wx)          + v11 * wy * wx;

    __shared__ float red[4];
    float s = v * v;
    #pragma unroll
    for (int o = 16; o > 0; o >>= 1) s += __shfl_down_sync(0xffffffffu, s, o);
    if ((c & 31) == 0) red[c >> 5] = s;
    __syncthreads();
    float tot = red[0] + red[1] + red[2] + red[3];
    float* dst = GD ? g_gd : g_wa;
    dst[(size_t)idx * CC + c] = v / (sqrtf(tot) + 1e-8f);
}

// ---------------------------------------------------------------------------
__device__ __forceinline__ float compute_vis(const float* __restrict__ kp1,
                                             const float* __restrict__ homo,
                                             int b, int n) {
    float kx = kp1[(size_t)(b * NN + n) * 2 + 0];
    float ky = kp1[(size_t)(b * NN + n) * 2 + 1];
    const float* hm = homo + b * 9;
    float den = hm[6] * kx + hm[7] * ky + hm[8] + 1e-8f;
    float wkx = (hm[0] * kx + hm[1] * ky + hm[2]) / den;
    float wky = (hm[3] * kx + hm[4] * ky + hm[5]) / den;
    return (wkx >= 0.0f && wkx <= (float)(WW - 1) &&
            wky >= 0.0f && wky <= (float)(HH - 1)) ? 1.0f : 0.0f;
}

// ---------------------------------------------------------------------------
// Main kernel. Blocks [0,256): FOS; [256,512): SOS.
// f32x2 FMA inner loop; masking fused at dots-write (dot domain, masked=-1e30);
// double-buffered dots, register-prefetched g tile, 2 barriers/chunk.
// ---------------------------------------------------------------------------
__global__ __launch_bounds__(256, 2) void main_kernel(const float* __restrict__ w_kp1) {
    extern __shared__ float sm[];
    float* aT   = sm;                        // [128][ST]
    float* gT   = aT + 128 * ST;             // [128][ST]
    float* dbuf = gT + 128 * ST;             // [2][64][SD]
    float* qxy  = dbuf + 2 * 64 * SD;        // [64][2]
    float* wc   = qxy + 128;                 // [64][2]

    int tid = threadIdx.x;
    int bid = blockIdx.x;
    bool is_sos = bid >= HALF_BLOCKS;
    int lbid = is_sos ? bid - HALF_BLOCKS : bid;
    int ms = lbid & (MSPLIT - 1);
    int qt = (lbid >> 2) & (QTILES - 1);
    int b  = lbid >> 6;
    int n0 = qt * TQ;
    int m_base = ms * COLS_PER_SPLIT;

    const float* qsrc = is_sos ? g_wa : g_a;
    const float* csrc = is_sos ? g_wa : g_gd;
    const int crows = is_sos ? NN : MM;

    // query tile transposed
    for (int idx = tid; idx < TQ * 32; idx += 256) {
        int r = idx & 63, k4 = idx >> 6;
        float4 v = *(const float4*)&qsrc[(size_t)(b * NN + n0 + r) * CC + 4 * k4];
        aT[(4 * k4 + 0) * ST + r] = v.x;
        aT[(4 * k4 + 1) * ST + r] = v.y;
        aT[(4 * k4 + 2) * ST + r] = v.z;
        aT[(4 * k4 + 3) * ST + r] = v.w;
    }
    if (tid < 128) qxy[tid] = w_kp1[(size_t)(b * NN + n0) * 2 + tid];

    // prefetch chunk 0
    float4 pf[8];
    #pragma unroll
    for (int j = 0; j < 8; j++) {
        int idx = tid + j * 256; int r = idx & 63, k4 = idx >> 6;
        pf[j] = *(const float4*)&csrc[(size_t)(b * crows + m_base + r) * CC + 4 * k4];
    }

    // selection state: 4 threads/row, keep 8 LARGEST dots
    int selr = tid >> 2, selq = tid & 3;
    float vals[8];
    int   idxs[8];
    #pragma unroll
    for (int j = 0; j < 8; j++) { vals[j] = -1e30f; idxs[j] = 0; }
    float worst = -1e30f;    // minimum of list

    int tx = tid & 15, ty = tid >> 4;

    for (int ch = 0; ch < CHUNKS; ch++) {
        int p = ch & 1;
        int m0 = m_base + ch * TMC;
        __syncthreads();   // B1: gT free, dbuf[p] free
        #pragma unroll
        for (int j = 0; j < 8; j++) {
            int idx = tid + j * 256; int r = idx & 63, k4 = idx >> 6;
            float4 v = pf[j];
            gT[(4 * k4 + 0) * ST + r] = v.x;
            gT[(4 * k4 + 1) * ST + r] = v.y;
            gT[(4 * k4 + 2) * ST + r] = v.z;
            gT[(4 * k4 + 3) * ST + r] = v.w;
        }
        if (is_sos && tid < 128) wc[tid] = w_kp1[(size_t)(b * NN + m0) * 2 + tid];
        __syncthreads();   // B2: gT + wc ready

        // prefetch next tile while computing
        if (ch + 1 < CHUNKS) {
            #pragma unroll
            for (int j = 0; j < 8; j++) {
                int idx = tid + j * 256; int r = idx & 63, k4 = idx >> 6;
                pf[j] = *(const float4*)&csrc[(size_t)(b * crows + m0 + TMC + r) * CC + 4 * k4];
            }
        }

        // f32x2 dot: accs = 4 rows x 2 col-pairs
        unsigned long long acc[8];
        #pragma unroll
        for (int j = 0; j < 8; j++) acc[j] = 0ULL;
        const float* ap = aT + 4 * ty;
        const float* gp = gT + 4 * tx;
        #pragma unroll 8
        for (int k = 0; k < CC; k++) {
            float4 av = *(const float4*)(ap + (size_t)k * ST);
            ulonglong2 gv = *(const ulonglong2*)(gp + (size_t)k * ST);
            unsigned long long ax, ay, az, aw;
            PACK2(ax, av.x); PACK2(ay, av.y); PACK2(az, av.z); PACK2(aw, av.w);
            FMA2(acc[0], ax, gv.x); FMA2(acc[1], ax, gv.y);
            FMA2(acc[2], ay, gv.x); FMA2(acc[3], ay, gv.y);
            FMA2(acc[4], az, gv.x); FMA2(acc[5], az, gv.y);
            FMA2(acc[6], aw, gv.x); FMA2(acc[7], aw, gv.y);
        }

        // masked dots write (dot domain)
        #pragma unroll
        for (int r = 0; r < 4; r++) {
            int row = 4 * ty + r;
            int n = n0 + row;
            float qx = qxy[row * 2 + 0], qy = qxy[row * 2 + 1];
            #pragma unroll
            for (int pp = 0; pp < 2; pp++) {
                float lo, hi;
                UNPACK2(lo, hi, acc[r * 2 + pp]);
                #pragma unroll
                for (int e = 0; e < 2; e++) {
                    float d = e ? hi : lo;
                    int col = 4 * tx + 2 * pp + e;
                    int m = m0 + col;
                    float cx, cy; bool em = false;
                    if (is_sos) {
                        cx = wc[col * 2 + 0]; cy = wc[col * 2 + 1];
                        em = (m == n);
                    } else {
                        cx = (float)((m & 31) * GRIDC + 4);
                        cy = (float)((m >> 5) * GRIDC + 4);
                    }
                    float dx = qx - cx, dy = qy - cy;
                    dbuf[p * 64 * SD + row * SD + col] =
                        ((dx * dx + dy * dy < 256.0f) || em) ? -1e30f : d;
                }
            }
        }

        // select previous chunk (overlaps with this phase)
        if (ch > 0) {
            const float* drow = dbuf + (1 - p) * 64 * SD + selr * SD + selq * 16;
            int mprev = m_base + (ch - 1) * TMC + selq * 16;
            #pragma unroll 4
            for (int ii = 0; ii < 16; ii++) {
                float val = drow[ii];
                if (val > worst) {
                    int m = mprev + ii;
                    bool done = false;
                    #pragma unroll
                    for (int j = 0; j < 8; j++)
                        if (!done && vals[j] == worst) {
                            vals[j] = val; idxs[j] = m; done = true;
                        }
                    worst = vals[0];
                    #pragma unroll
                    for (int j = 1; j < 8; j++) worst = fminf(worst, vals[j]);
                }
            }
        }
    }

    __syncthreads();   // dots of last chunk visible
    {
        const float* drow = dbuf + 1 * 64 * SD + selr * SD + selq * 16;
        int mlast = m_base + (CHUNKS - 1) * TMC + selq * 16;
        #pragma unroll 4
        for (int ii = 0; ii < 16; ii++) {
            float val = drow[ii];
            if (val > worst) {
                int m = mlast + ii;
                bool done = false;
                #pragma unroll
                for (int j = 0; j < 8; j++)
                    if (!done && vals[j] == worst) {
                        vals[j] = val; idxs[j] = m; done = true;
                    }
                worst = vals[0];
                #pragma unroll
                for (int j = 1; j < 8; j++) worst = fminf(worst, vals[j]);
            }
        }
    }

    // write partial lists into dbuf[0] region (reuse; select read dbuf[1] only)
    float* selv = dbuf;                 // [64][33]
    int*   seli = (int*)(dbuf + 64 * 33);
    {
        float* pv = selv + selr * 33 + selq * 8;
        int*   pi = seli + selr * 33 + selq * 8;
        #pragma unroll
        for (int j = 0; j < 8; j++) { pv[j] = vals[j]; pi[j] = idxs[j]; }
    }
    __syncthreads();

    // per-row merge: keep 8 largest dots of 32
    if (tid < TQ) {
        float mv[8]; int mi[8];
        #pragma unroll
        for (int j = 0; j < 8; j++) { mv[j] = -1e30f; mi[j] = 0; }
        float w8 = -1e30f;
        const float* pv = selv + tid * 33;
        const int*   pi = seli + tid * 33;
        #pragma unroll 4
        for (int i = 0; i < 32; i++) {
            float val = pv[i];
            if (val > w8) {
                int ii = pi[i];
                bool done = false;
                #pragma unroll
                for (int j = 0; j < 8; j++)
                    if (!done && mv[j] == w8) { mv[j] = val; mi[j] = ii; done = true; }
                w8 = mv[0];
                #pragma unroll
                for (int j = 1; j < 8; j++) w8 = fminf(w8, mv[j]);
            }
        }
        size_t base = (((size_t)(b * NN + n0 + tid)) * MSPLIT + ms) * 8;
        if (is_sos) {
            #pragma unroll
            for (int j = 0; j < 8; j++) {
                g_sos_topv[base + j] = mv[j];
                g_sos_topi[base + j] = mi[j];
            }
        } else {
            #pragma unroll
            for (int j = 0; j < 8; j++) g_fos_top[base + j] = mv[j];
        }
    }
}

// ---------------------------------------------------------------------------
// Warp bitonic sort (32 keys ascending, with payload)
// ---------------------------------------------------------------------------
__device__ __forceinline__ void bitonic32(float& v, int& i) {
    unsigned lane = threadIdx.x & 31;
    #pragma unroll
    for (int k = 2; k <= 32; k <<= 1) {
        #pragma unroll
        for (int j = k >> 1; j > 0; j >>= 1) {
            float pv = __shfl_xor_sync(0xffffffffu, v, j);
            int   pi = __shfl_xor_sync(0xffffffffu, i, j);
            bool up = ((lane & k) == 0) || (k == 32);
            bool keepmin = (up == ((lane & j) == 0));
            bool take = keepmin ? (pv < v) : (pv > v);
            if (take) { v = pv; i = pi; }
        }
    }
}

// ---------------------------------------------------------------------------
// Fused epilogue: warp per row; dot-domain merges (sort on -dot), convert,
// pos, vis, d1 gather; writes row-level partials.
// ---------------------------------------------------------------------------
__global__ __launch_bounds__(256) void epilogue_kernel(const float* __restrict__ kp1,
                                                       const float* __restrict__ homo) {
    int w = threadIdx.x >> 5, lane = threadIdx.x & 31;
    int row = blockIdx.x * 8 + w;
    int b = row >> 10, n = row & 1023;

    // pos = || a_row - wa_row ||
    float4 av = *(const float4*)&g_a [(size_t)row * CC + 4 * lane];
    float4 wv = *(const float4*)&g_wa[(size_t)row * CC + 4 * lane];
    float d0 = av.x - wv.x, d1 = av.y - wv.y, d2 = av.z - wv.z, d3 = av.w - wv.w;
    float s = d0 * d0 + d1 * d1 + d2 * d2 + d3 * d3;
    #pragma unroll
    for (int o = 16; o > 0; o >>= 1) s += __shfl_xor_sync(0xffffffffu, s, o);
    float pos = sqrtf(s);

    // ---- FOS: sort on -dot ascending -> lanes 0..7 = largest dots ----
    float fneg = -g_fos_top[(size_t)row * 32 + lane];
    int   fdmy = 0;
    bitonic32(fneg, fdmy);
    float fdist = (fneg > 1e29f) ? 10.0f
                                 : sqrtf(fmaxf(2.0f + 2.0f * fneg, 0.0f) + 1e-8f);
    // note: dot = -fneg -> 2 - 2*dot = 2 + 2*fneg
    float f = (lane < 8) ? fmaxf(pos - fdist + 1.0f, 0.0f) : 0.0f;
    #pragma unroll
    for (int o = 16; o > 0; o >>= 1) f += __shfl_xor_sync(0xffffffffu, f, o);

    // ---- SOS ----
    float sneg = -g_sos_topv[(size_t)row * 32 + lane];
    int   si   =  g_sos_topi[(size_t)row * 32 + lane];
    bitonic32(sneg, si);

    int j = lane >> 2, q = lane & 3;
    float d2neg = __shfl_sync(0xffffffffu, sneg, j);
    int   cidx  = __shfl_sync(0xffffffffu, si, j);
    const float4* pa = (const float4*)(g_a + (size_t)row * CC);
    const float4* pb = (const float4*)(g_a + (size_t)(b * NN + cidx) * CC);
    float dp = 0.0f;
    #pragma unroll
    for (int kk = 0; kk < 8; kk++) {
        float4 x = pa[q * 8 + kk], y = pb[q * 8 + kk];
        dp += x.x * y.x + x.y * y.y + x.z * y.z + x.w * y.w;
    }
    dp += __shfl_xor_sync(0xffffffffu, dp, 1);
    dp += __shfl_xor_sync(0xffffffffu, dp, 2);
    float d1v = sqrtf(fmaxf(2.0f - 2.0f * dp, 0.0f) + 1e-8f);
    float d2v = sqrtf(fmaxf(2.0f + 2.0f * d2neg, 0.0f) + 1e-8f);
    float t = (d2neg < 1e29f) ? (d1v - d2v) : 0.0f;   // ok-mask: unmasked dot
    float t2 = (q == 0) ? t * t : 0.0f;
    #pragma unroll
    for (int o = 16; o > 0; o >>= 1) t2 += __shfl_xor_sync(0xffffffffu, t2, o);

    if (lane == 0) {
        float vis = compute_vis(kp1, homo, b, n);
        g_fos_row[row] = f * vis;
        g_vis_row[row] = vis;
        g_sos_row[row] = sqrtf(t2 + 1e-8f) * vis;
    }
}

// ---------------------------------------------------------------------------
__global__ void finalize_kernel(float* __restrict__ out) {
    __shared__ float sf[1024], sv[1024], ss[1024];
    int t = threadIdx.x;
    float f = 0.0f, v = 0.0f, s = 0.0f;
    #pragma unroll
    for (int i = 0; i < 4; i++) {
        f += g_fos_row[t + 1024 * i];
        v += g_vis_row[t + 1024 * i];
        s += g_sos_row[t + 1024 * i];
    }
    sf[t] = f; sv[t] = v; ss[t] = s;
    __syncthreads();
    for (int o = 512; o > 0; o >>= 1) {
        if (t < o) {
            sf[t] += sf[t + o];
            sv[t] += sv[t + o];
            ss[t] += ss[t + o];
        }
        __syncthreads();
    }
    if (t == 0) {
        float cnt = fmaxf(sv[0], 1.0f);
        out[0] = sf[0] / (cnt * 8.0f) + ss[0] / cnt;
    }
}

// ---------------------------------------------------------------------------
extern "C" void kernel_launch(void* const* d_in, const int* in_sizes, int n_in,
                              void* d_out, int out_size) {
    const float* kp1      = (const float*)d_in[0];
    const float* w_kp1    = (const float*)d_in[1];
    const float* kp1_desc = (const float*)d_in[2];
    const float* desc2    = (const float*)d_in[3];
    const float* homo12   = (const float*)d_in[4];
    (void)in_sizes; (void)n_in; (void)out_size;

    cudaFuncSetAttribute(main_kernel,
                         cudaFuncAttributeMaxDynamicSharedMemorySize, SMEM_BYTES);

    prep_a_kernel<<<BB * NN, CC>>>(kp1_desc);
    prep_bil_kernel<false><<<BB * NN, CC>>>(w_kp1, desc2);
    prep_bil_kernel<true ><<<BB * MM, CC>>>(w_kp1, desc2);
    main_kernel<<<MAIN_BLOCKS, 256, SMEM_BYTES>>>(w_kp1);
    epilogue_kernel<<<BB * NN / 8, 256>>>(kp1, homo12);
    finalize_kernel<<<1, 1024>>>((float*)d_out);
}

// round 6
// speedup vs baseline: 3.6144x; 1.0933x over previous
#include <cuda_runtime.h>
#include <math.h>

// Problem constants
#define BB 4
#define NN 1024
#define CC 128
#define HH 256
#define WW 256
#define MM 1024
#define GRIDC 8

#define TQ 64
#define TMC 64
#define MSPLIT 2
#define COLS_PER_SPLIT (MM / MSPLIT)      // 512
#define CHUNKS (COLS_PER_SPLIT / TMC)     // 8
#define QTILES (NN / TQ)                  // 16
#define HALF_BLOCKS (BB * QTILES * MSPLIT) // 128
#define MAIN_BLOCKS (2 * HALF_BLOCKS)      // 256
#define NTOP (MSPLIT * 8)                  // 16 per row

#define ST 68   // tile row stride in floats; 68*4=272B = multiple of 16 (vector-load safe)
// smem: aT[128][ST] + gT[128][ST] + wc[64][2]; endgame stage reuses gT
#define SMEM_FLOATS (128 * ST * 2 + 2 * TMC)
#define SMEM_BYTES (SMEM_FLOATS * 4)

#define PACK2(dst, x) asm("mov.b64 %0, {%1, %1};" : "=l"(dst) : "r"(__float_as_uint(x)))
#define FMA2(acc, a, b) asm("fma.rn.f32x2 %0, %1, %2, %0;" : "+l"(acc) : "l"(a), "l"(b))
#define UNPACK2(lo, hi, v) asm("mov.b64 {%0, %1}, %2;" : "=f"(lo), "=f"(hi) : "l"(v))

// Scratch (device globals)
__device__ float g_a [BB * NN * CC];
__device__ float g_wa[BB * NN * CC];
__device__ float g_gd[BB * MM * CC];
__device__ float g_fos_top [BB * NN * NTOP];   // dots
__device__ float g_sos_topv[BB * NN * NTOP];   // dots
__device__ int   g_sos_topi[BB * NN * NTOP];
__device__ float g_fos_row[BB * NN];
__device__ float g_vis_row[BB * NN];
__device__ float g_sos_row[BB * NN];

// ---------------------------------------------------------------------------
// Prep: normalize anchors + bilinear-sample & normalize wa / gd (fused).
// ---------------------------------------------------------------------------
__global__ void prep_kernel(const float* __restrict__ kp1_desc,
                            const float* __restrict__ w_kp1,
                            const float* __restrict__ desc2) {
    int idx = blockIdx.x;
    const int per_b = 2 * NN + MM;
    int b = idx / per_b;
    int i = idx - b * per_b;
    int c = threadIdx.x;

    float v;
    float* dst;
    if (i < NN) {
        v   = kp1_desc[(size_t)(b * NN + i) * CC + c];
        dst = g_a + (size_t)(b * NN + i) * CC;
    } else {
        float px, py;
        if (i < 2 * NN) {
            int n = i - NN;
            px  = w_kp1[(size_t)(b * NN + n) * 2 + 0];
            py  = w_kp1[(size_t)(b * NN + n) * 2 + 1];
            dst = g_wa + (size_t)(b * NN + n) * CC;
        } else {
            int m = i - 2 * NN;
            px  = ((float)(m & 31) + 0.5f) * (float)GRIDC;
            py  = ((float)(m >> 5) + 0.5f) * (float)GRIDC;
            dst = g_gd + (size_t)(b * MM + m) * CC;
        }
        float x = fminf(fmaxf(px, 0.0f), (float)(WW - 1));
        float y = fminf(fmaxf(py, 0.0f), (float)(HH - 1));
        float x0f = floorf(x), y0f = floorf(y);
        float wx = x - x0f, wy = y - y0f;
        int x0 = (int)x0f, y0 = (int)y0f;
        int x1 = min(x0 + 1, WW - 1), y1 = min(y0 + 1, HH - 1);
        const float* base = desc2 + (size_t)(b * CC + c) * (HH * WW);
        float v00 = base[y0 * WW + x0];
        float v01 = base[y0 * WW + x1];
        float v10 = base[y1 * WW + x0];
        float v11 = base[y1 * WW + x1];
        v = v00 * (1.0f - wy) * (1.0f - wx) + v01 * (1.0f - wy) * wx
          + v10 * wy * (1.0f - wx)          + v11 * wy * wx;
    }

    __shared__ float red[4];
    float s = v * v;
    #pragma unroll
    for (int o = 16; o > 0; o >>= 1) s += __shfl_down_sync(0xffffffffu, s, o);
    if ((c & 31) == 0) red[c >> 5] = s;
    __syncthreads();
    float tot = red[0] + red[1] + red[2] + red[3];
    dst[c] = v / (sqrtf(tot) + 1e-8f);
}

// ---------------------------------------------------------------------------
__device__ __forceinline__ float compute_vis(const float* __restrict__ kp1,
                                             const float* __restrict__ homo,
                                             int b, int n) {
    float kx = kp1[(size_t)(b * NN + n) * 2 + 0];
    float ky = kp1[(size_t)(b * NN + n) * 2 + 1];
    const float* hm = homo + b * 9;
    float den = hm[6] * kx + hm[7] * ky + hm[8] + 1e-8f;
    float wkx = (hm[0] * kx + hm[1] * ky + hm[2]) / den;
    float wky = (hm[3] * kx + hm[4] * ky + hm[5]) / den;
    return (wkx >= 0.0f && wkx <= (float)(WW - 1) &&
            wky >= 0.0f && wky <= (float)(HH - 1)) ? 1.0f : 0.0f;
}

// ---------------------------------------------------------------------------
// Main kernel. Blocks [0,128): FOS; [128,256): SOS.
// 64x64 tiles per chunk, 8 chunks of candidates. f32x2 FMA inner loop.
// No dots smem: intra-warp shuffle transpose -> per-lane register top-8.
// ---------------------------------------------------------------------------
__global__ __launch_bounds__(256, 3) void main_kernel(const float* __restrict__ w_kp1) {
    extern __shared__ float sm[];
    float* aT = sm;                    // [128][ST]
    float* gT = aT + 128 * ST;         // [128][ST]
    float* wc = gT + 128 * ST;         // [64][2]

    int tid = threadIdx.x;
    int lane = tid & 31;
    int warp = tid >> 5;
    int bid = blockIdx.x;
    bool is_sos = bid >= HALF_BLOCKS;
    int lbid = is_sos ? bid - HALF_BLOCKS : bid;
    int ms = lbid & (MSPLIT - 1);
    int qt = (lbid >> 1) & (QTILES - 1);
    int b  = lbid >> 5;
    int n0 = qt * TQ;
    int m_base = ms * COLS_PER_SPLIT;

    const float* qsrc = is_sos ? g_wa : g_a;
    const float* csrc = is_sos ? g_wa : g_gd;
    const int crows = is_sos ? NN : MM;

    // query tile transposed: aT[k][r]
    for (int idx = tid; idx < TQ * 32; idx += 256) {
        int r = idx & 63, k4 = idx >> 6;
        float4 v = *(const float4*)&qsrc[(size_t)(b * NN + n0 + r) * CC + 4 * k4];
        aT[(4 * k4 + 0) * ST + r] = v.x;
        aT[(4 * k4 + 1) * ST + r] = v.y;
        aT[(4 * k4 + 2) * ST + r] = v.z;
        aT[(4 * k4 + 3) * ST + r] = v.w;
    }

    // selection identity: after transpose, this lane owns one row, 16 cols/chunk
    int Rl = lane >> 2;             // 0..7 (row within warp)
    int qq = lane & 3;              // col quarter
    int r_d = Rl & 3;
    int s_base = ((Rl >> 2) << 4) + 4 * qq;
    int row_loc = 8 * warp + Rl;    // 0..63
    int n_glob = n0 + row_loc;
    float qx = w_kp1[(size_t)(b * NN + n_glob) * 2 + 0];
    float qy = w_kp1[(size_t)(b * NN + n_glob) * 2 + 1];

    float vals[8];
    int   idxs[8];
    #pragma unroll
    for (int j = 0; j < 8; j++) { vals[j] = -1e30f; idxs[j] = 0; }
    float worst = -1e30f;

    int tx = tid & 15, ty = tid >> 4;

    // prefetch chunk 0 (first half of tile)
    float4 pf[4];
    #pragma unroll
    for (int j = 0; j < 4; j++) {
        int idx = tid + j * 256; int r = idx & 63, k4 = idx >> 6;
        pf[j] = *(const float4*)&csrc[(size_t)(b * crows + m_base + r) * CC + 4 * k4];
    }

    for (int ch = 0; ch < CHUNKS; ch++) {
        int m0 = m_base + ch * TMC;
        __syncthreads();   // B1: gT/wc free
        #pragma unroll
        for (int j = 0; j < 4; j++) {
            int idx = tid + j * 256; int r = idx & 63, k4 = idx >> 6;
            float4 v = pf[j];
            gT[(4 * k4 + 0) * ST + r] = v.x;
            gT[(4 * k4 + 1) * ST + r] = v.y;
            gT[(4 * k4 + 2) * ST + r] = v.z;
            gT[(4 * k4 + 3) * ST + r] = v.w;
        }
        #pragma unroll
        for (int j = 4; j < 8; j++) {
            int idx = tid + j * 256; int r = idx & 63, k4 = idx >> 6;
            float4 v = *(const float4*)&csrc[(size_t)(b * crows + m0 + r) * CC + 4 * k4];
            gT[(4 * k4 + 0) * ST + r] = v.x;
            gT[(4 * k4 + 1) * ST + r] = v.y;
            gT[(4 * k4 + 2) * ST + r] = v.z;
            gT[(4 * k4 + 3) * ST + r] = v.w;
        }
        if (is_sos && tid < 128) wc[tid] = w_kp1[(size_t)(b * NN + m0) * 2 + tid];
        __syncthreads();   // B2: tile ready

        if (ch + 1 < CHUNKS) {
            #pragma unroll
            for (int j = 0; j < 4; j++) {
                int idx = tid + j * 256; int r = idx & 63, k4 = idx >> 6;
                pf[j] = *(const float4*)&csrc[(size_t)(b * crows + m0 + TMC + r) * CC + 4 * k4];
            }
        }

        // dot loop: 4 rows x 4 cols, accs as f32x2 col-pairs
        unsigned long long acc[8];
        #pragma unroll
        for (int j = 0; j < 8; j++) acc[j] = 0ULL;
        const float* ap = aT + 4 * ty;
        const float* gp = gT + 4 * tx;
        #pragma unroll 8
        for (int k = 0; k < CC; k++) {
            float4 av = *(const float4*)(ap + (size_t)k * ST);
            ulonglong2 gv = *(const ulonglong2*)(gp + (size_t)k * ST);
            unsigned long long a0, a1, a2, a3;
            PACK2(a0, av.x); PACK2(a1, av.y); PACK2(a2, av.z); PACK2(a3, av.w);
            FMA2(acc[0], a0, gv.x); FMA2(acc[1], a0, gv.y);
            FMA2(acc[2], a1, gv.x); FMA2(acc[3], a1, gv.y);
            FMA2(acc[4], a2, gv.x); FMA2(acc[5], a2, gv.y);
            FMA2(acc[6], a3, gv.x); FMA2(acc[7], a3, gv.y);
        }

        // intra-warp transpose: lane -> 1 row x 16 cols (8 f32x2)
        unsigned long long myv[8];
        #pragma unroll
        for (int r = 0; r < 4; r++) {
            #pragma unroll
            for (int cp = 0; cp < 2; cp++) {
                #pragma unroll
                for (int off = 0; off < 4; off++) {
                    unsigned long long v =
                        __shfl_sync(0xffffffffu, acc[r * 2 + cp], s_base + off);
                    if (r_d == r) myv[2 * off + cp] = v;
                }
            }
        }

        // mask + insert into per-lane top-8 (dot domain; masked = -1e30)
        #pragma unroll
        for (int jp = 0; jp < 8; jp++) {
            float lo, hi; UNPACK2(lo, hi, myv[jp]);
            #pragma unroll
            for (int e = 0; e < 2; e++) {
                int col = 16 * qq + 2 * jp + e;
                float d = e ? hi : lo;
                int m = m0 + col;
                float cx, cy; bool em = false;
                if (is_sos) {
                    cx = wc[2 * col]; cy = wc[2 * col + 1];
                    em = (m == n_glob);
                } else {
                    cx = (float)((m & 31) * GRIDC + 4);
                    cy = (float)((m >> 5) * GRIDC + 4);
                }
                float dx = qx - cx, dy = qy - cy;
                float val = ((dx * dx + dy * dy < 256.0f) || em) ? -1e30f : d;
                if (val > worst) {
                    bool done = false;
                    #pragma unroll
                    for (int j = 0; j < 8; j++)
                        if (!done && vals[j] == worst) {
                            vals[j] = val; idxs[j] = m; done = true;
                        }
                    worst = vals[0];
                    #pragma unroll
                    for (int j = 1; j < 8; j++) worst = fminf(worst, vals[j]);
                }
            }
        }
    }

    // endgame: stage 4 lanes x 8 candidates per row into freed gT
    __syncthreads();
    float* sgv = gT;                         // [64][32]
    int*   sgi = (int*)(gT + 64 * 32);       // [64][32]
    {
        float* pv = sgv + row_loc * 32 + qq * 8;
        int*   pi = sgi + row_loc * 32 + qq * 8;
        #pragma unroll
        for (int j = 0; j < 8; j++) { pv[j] = vals[j]; pi[j] = idxs[j]; }
    }
    __syncthreads();

    if (tid < TQ) {
        float mv[8]; int mi[8];
        #pragma unroll
        for (int j = 0; j < 8; j++) { mv[j] = -1e30f; mi[j] = 0; }
        float w8 = -1e30f;
        const float* pv = sgv + tid * 32;
        const int*   pi = sgi + tid * 32;
        #pragma unroll 4
        for (int i = 0; i < 32; i++) {
            float val = pv[i];
            if (val > w8) {
                int ii = pi[i];
                bool done = false;
                #pragma unroll
                for (int j = 0; j < 8; j++)
                    if (!done && mv[j] == w8) { mv[j] = val; mi[j] = ii; done = true; }
                w8 = mv[0];
                #pragma unroll
                for (int j = 1; j < 8; j++) w8 = fminf(w8, mv[j]);
            }
        }
        size_t base = (size_t)(b * NN + n0 + tid) * NTOP + ms * 8;
        if (is_sos) {
            #pragma unroll
            for (int j = 0; j < 8; j++) {
                g_sos_topv[base + j] = mv[j];
                g_sos_topi[base + j] = mi[j];
            }
        } else {
            #pragma unroll
            for (int j = 0; j < 8; j++) g_fos_top[base + j] = mv[j];
        }
    }
}

// ---------------------------------------------------------------------------
__device__ __forceinline__ void bitonic32(float& v, int& i) {
    unsigned lane = threadIdx.x & 31;
    #pragma unroll
    for (int k = 2; k <= 32; k <<= 1) {
        #pragma unroll
        for (int j = k >> 1; j > 0; j >>= 1) {
            float pv = __shfl_xor_sync(0xffffffffu, v, j);
            int   pi = __shfl_xor_sync(0xffffffffu, i, j);
            bool up = ((lane & k) == 0) || (k == 32);
            bool keepmin = (up == ((lane & j) == 0));
            bool take = keepmin ? (pv < v) : (pv > v);
            if (take) { v = pv; i = pi; }
        }
    }
}

// ---------------------------------------------------------------------------
// Epilogue: warp per row; dot-domain merges (sort -dot asc), pos, vis, d1.
// ---------------------------------------------------------------------------
__global__ __launch_bounds__(256) void epilogue_kernel(const float* __restrict__ kp1,
                                                       const float* __restrict__ homo) {
    int w = threadIdx.x >> 5, lane = threadIdx.x & 31;
    int row = blockIdx.x * 8 + w;
    int b = row >> 10, n = row & 1023;

    float4 av = *(const float4*)&g_a [(size_t)row * CC + 4 * lane];
    float4 wv = *(const float4*)&g_wa[(size_t)row * CC + 4 * lane];
    float d0 = av.x - wv.x, d1 = av.y - wv.y, d2 = av.z - wv.z, d3 = av.w - wv.w;
    float s = d0 * d0 + d1 * d1 + d2 * d2 + d3 * d3;
    #pragma unroll
    for (int o = 16; o > 0; o >>= 1) s += __shfl_xor_sync(0xffffffffu, s, o);
    float pos = sqrtf(s);

    // ---- FOS: 16 partials, pad rest ----
    float fneg = (lane < NTOP) ? -g_fos_top[(size_t)row * NTOP + lane] : 1e30f;
    int   fdmy = 0;
    bitonic32(fneg, fdmy);
    float fdist = (fneg > 1e29f) ? 10.0f
                                 : sqrtf(fmaxf(2.0f + 2.0f * fneg, 0.0f) + 1e-8f);
    float f = (lane < 8) ? fmaxf(pos - fdist + 1.0f, 0.0f) : 0.0f;
    #pragma unroll
    for (int o = 16; o > 0; o >>= 1) f += __shfl_xor_sync(0xffffffffu, f, o);

    // ---- SOS ----
    float sneg = (lane < NTOP) ? -g_sos_topv[(size_t)row * NTOP + lane] : 1e30f;
    int   si   = (lane < NTOP) ?  g_sos_topi[(size_t)row * NTOP + lane] : 0;
    bitonic32(sneg, si);

    int j = lane >> 2, q = lane & 3;
    float d2neg = __shfl_sync(0xffffffffu, sneg, j);
    int   cidx  = __shfl_sync(0xffffffffu, si, j);
    const float4* pa = (const float4*)(g_a + (size_t)row * CC);
    const float4* pb = (const float4*)(g_a + (size_t)(b * NN + cidx) * CC);
    float dp = 0.0f;
    #pragma unroll
    for (int kk = 0; kk < 8; kk++) {
        float4 x = pa[q * 8 + kk], y = pb[q * 8 + kk];
        dp += x.x * y.x + x.y * y.y + x.z * y.z + x.w * y.w;
    }
    dp += __shfl_xor_sync(0xffffffffu, dp, 1);
    dp += __shfl_xor_sync(0xffffffffu, dp, 2);
    float d1v = sqrtf(fmaxf(2.0f - 2.0f * dp, 0.0f) + 1e-8f);
    float d2v = sqrtf(fmaxf(2.0f + 2.0f * d2neg, 0.0f) + 1e-8f);
    float t = (d2neg < 1e29f) ? (d1v - d2v) : 0.0f;
    float t2 = (q == 0) ? t * t : 0.0f;
    #pragma unroll
    for (int o = 16; o > 0; o >>= 1) t2 += __shfl_xor_sync(0xffffffffu, t2, o);

    if (lane == 0) {
        float vis = compute_vis(kp1, homo, b, n);
        g_fos_row[row] = f * vis;
        g_vis_row[row] = vis;
        g_sos_row[row] = sqrtf(t2 + 1e-8f) * vis;
    }
}

// ---------------------------------------------------------------------------
__global__ void finalize_kernel(float* __restrict__ out) {
    __shared__ float sf[1024], sv[1024], ss[1024];
    int t = threadIdx.x;
    float f = 0.0f, v = 0.0f, s = 0.0f;
    #pragma unroll
    for (int i = 0; i < 4; i++) {
        f += g_fos_row[t + 1024 * i];
        v += g_vis_row[t + 1024 * i];
        s += g_sos_row[t + 1024 * i];
    }
    sf[t] = f; sv[t] = v; ss[t] = s;
    __syncthreads();
    for (int o = 512; o > 0; o >>= 1) {
        if (t < o) {
            sf[t] += sf[t + o];
            sv[t] += sv[t + o];
            ss[t] += ss[t + o];
        }
        __syncthreads();
    }
    if (t == 0) {
        float cnt = fmaxf(sv[0], 1.0f);
        out[0] = sf[0] / (cnt * 8.0f) + ss[0] / cnt;
    }
}

// ---------------------------------------------------------------------------
extern "C" void kernel_launch(void* const* d_in, const int* in_sizes, int n_in,
                              void* d_out, int out_size) {
    const float* kp1      = (const float*)d_in[0];
    const float* w_kp1    = (const float*)d_in[1];
    const float* kp1_desc = (const float*)d_in[2];
    const float* desc2    = (const float*)d_in[3];
    const float* homo12   = (const float*)d_in[4];
    (void)in_sizes; (void)n_in; (void)out_size;

    cudaFuncSetAttribute(main_kernel,
                         cudaFuncAttributeMaxDynamicSharedMemorySize, SMEM_BYTES);

    prep_kernel<<<BB * (2 * NN + MM), CC>>>(kp1_desc, w_kp1, desc2);
    main_kernel<<<MAIN_BLOCKS, 256, SMEM_BYTES>>>(w_kp1);
    epilogue_kernel<<<BB * NN / 8, 256>>>(kp1, homo12);
    finalize_kernel<<<1, 1024>>>((float*)d_out);
}